// round 17
// baseline (speedup 1.0000x reference)
#include <cuda_runtime.h>
#include <cuda_fp16.h>
#include <cstdint>
#include <math.h>

// Problem constants
#define NN_MAX 100096
#define HDIM 128
#define EMAX 3400000

// ---------------- scratch (device globals; no allocation allowed) ------------
__device__ __half g_mh[NN_MAX * HDIM];          // x @ W   (fp16 messages)
__device__ float g_gh[NN_MAX * 3 * HDIM];       // x @ gru_w_hh^T + b_hh
__device__ float g_agg[NN_MAX * HDIM];          // mean-aggregated messages
__device__ float g_gi[NN_MAX * 3 * HDIM];       // agg @ gru_w_ih^T + b_ih
__device__ float g_hconv[NN_MAX * HDIM];        // GRU output
__device__ float g_gates[NN_MAX * 3 * HDIM];    // lstm gates, compact [i,g,o]
__device__ float g_wt[HDIM * HDIM];             // W^T
__device__ int   g_degi[NN_MAX];
__device__ int   g_cursor[NN_MAX];
__device__ int   g_off[NN_MAX + 1];
__device__ int   g_csr[EMAX];
__device__ int   g_idx64;

// ---------------- index-width detection --------------------------------------
__global__ void detect_kernel(const void* edges) {
    const int* p = (const int*)edges;
    int z = 0;
#pragma unroll
    for (int i = 0; i < 8; i++) z += (p[2 * i + 1] == 0) ? 1 : 0;
    g_idx64 = (z == 8) ? 1 : 0;
}

__global__ void zero_deg_kernel(int M) {
    int i = blockIdx.x * blockDim.x + threadIdx.x;
    if (i < M) g_degi[i] = 0;
}

__global__ void transposeW_kernel(const float* __restrict__ W) {
    int i = blockIdx.x * blockDim.x + threadIdx.x;
    if (i < HDIM * HDIM) {
        int r = i >> 7;
        int c = i & 127;
        g_wt[c * HDIM + r] = W[i];
    }
}

// ---------------- CSR build -----------------------------------------------
__global__ void hist_kernel(const void* __restrict__ edges, int E) {
    const bool is64 = (g_idx64 != 0);
    const long long* p64 = (const long long*)edges;
    const int* p32 = (const int*)edges;
    int stride = gridDim.x * blockDim.x;
    for (int e = blockIdx.x * blockDim.x + threadIdx.x; e < E; e += stride) {
        int dst = is64 ? (int)p64[E + e] : p32[E + e];
        atomicAdd(&g_degi[dst], 1);
    }
}

__global__ void scan_kernel(int M) {
    __shared__ int warpsums[32];
    const int tid = threadIdx.x;
    const int lane = tid & 31;
    const int wid = tid >> 5;
    int running = 0;
    for (int base = 0; base < M; base += 1024) {
        int i = base + tid;
        int v = (i < M) ? g_degi[i] : 0;
        int s = v;
#pragma unroll
        for (int o = 1; o < 32; o <<= 1) {
            int t = __shfl_up_sync(0xffffffffu, s, o);
            if (lane >= o) s += t;
        }
        if (lane == 31) warpsums[wid] = s;
        __syncthreads();
        if (wid == 0) {
            int ws = warpsums[lane];
#pragma unroll
            for (int o = 1; o < 32; o <<= 1) {
                int t = __shfl_up_sync(0xffffffffu, ws, o);
                if (lane >= o) ws += t;
            }
            warpsums[lane] = ws;
        }
        __syncthreads();
        int warpBase = (wid == 0) ? 0 : warpsums[wid - 1];
        int excl = running + warpBase + s - v;
        if (i < M) {
            g_off[i] = excl;
            g_cursor[i] = excl;
        }
        int chunkTotal = warpsums[31];
        __syncthreads();
        running += chunkTotal;
    }
    if (tid == 0) g_off[M] = running;
}

__global__ void fill_kernel(const void* __restrict__ edges, int E) {
    const bool is64 = (g_idx64 != 0);
    const long long* p64 = (const long long*)edges;
    const int* p32 = (const int*)edges;
    int stride = gridDim.x * blockDim.x;
    for (int e = blockIdx.x * blockDim.x + threadIdx.x; e < E; e += stride) {
        int src, dst;
        if (is64) {
            src = (int)p64[e];
            dst = (int)p64[E + e];
        } else {
            src = p32[e];
            dst = p32[E + e];
        }
        int pos = atomicAdd(&g_cursor[dst], 1);
        g_csr[pos] = src;
    }
}

// ---------------- gather: one warp per dst, fp16 messages, mean fused ---------
__global__ void gather_kernel(const __half* __restrict__ mh, int M) {
    int w = (blockIdx.x * blockDim.x + threadIdx.x) >> 5;
    if (w >= M) return;
    int lane = threadIdx.x & 31;
    int start = g_off[w];
    int end = g_off[w + 1];
    float ax = 0.f, ay = 0.f, az = 0.f, aw = 0.f;
    int e = start;
    for (; e + 3 < end; e += 4) {
#pragma unroll
        for (int q = 0; q < 4; q++) {
            int s0 = g_csr[e + q];
            uint2 u = *(const uint2*)(mh + (size_t)s0 * HDIM + lane * 4);
            float2 f0 = __half22float2(*reinterpret_cast<__half2*>(&u.x));
            float2 f1 = __half22float2(*reinterpret_cast<__half2*>(&u.y));
            ax += f0.x; ay += f0.y; az += f1.x; aw += f1.y;
        }
    }
    for (; e < end; e++) {
        int s0 = g_csr[e];
        uint2 u = *(const uint2*)(mh + (size_t)s0 * HDIM + lane * 4);
        float2 f0 = __half22float2(*reinterpret_cast<__half2*>(&u.x));
        float2 f1 = __half22float2(*reinterpret_cast<__half2*>(&u.y));
        ax += f0.x; ay += f0.y; az += f1.x; aw += f1.y;
    }
    float inv = 1.0f / fmaxf((float)(end - start), 1.0f);
    float4 o = make_float4(ax * inv, ay * inv, az * inv, aw * inv);
    *(float4*)(g_agg + (size_t)w * HDIM + lane * 4) = o;
}

// =====================================================================
// fp16 two-term tensor-core GEMM (mma.sync), HIGH-OCCUPANCY tile:
//   BM=64, BN=64, K=128; 256 thr = 8 warps (4 m-slots x 2 n-slots),
//   warp tile 16x32. smem 52224 B + regs<=64 -> 4 CTAs/SM (32 warps).
//   A = Ahi + Alo (fp16 pair); B = fp16(B); C = Ahi*B + Alo*B.
// In-block col-tile loop, A loaded+split once. Two output phases:
//   phase 1 (t < nT1): B1 tiles -> C1h (fp16 store, no bias)   [m = x@W]
//   phase 2:           B2 tiles -> C2 (fp32 + bias(+bias2))
// gateSkip (phase 2): tile tt reads B2 rows {0,64,256,320,384,448}[tt].
// =====================================================================
#define SROW 136
#define OFF_A_HI 0
#define OFF_A_LO (64 * SROW * 2)              // 17408
#define OFF_B    (2 * 64 * SROW * 2)          // 34816
#define SMEM_BYTES (2 * 64 * SROW * 2 + 64 * SROW * 2)   // 52224

__device__ __forceinline__ void ldsm4(uint32_t& r0, uint32_t& r1, uint32_t& r2,
                                      uint32_t& r3, uint32_t addr) {
    asm volatile("ldmatrix.sync.aligned.m8n8.x4.shared.b16 {%0,%1,%2,%3}, [%4];"
                 : "=r"(r0), "=r"(r1), "=r"(r2), "=r"(r3) : "r"(addr));
}

__device__ __forceinline__ void mma_f16(float* c, const uint32_t* a,
                                        uint32_t b0, uint32_t b1) {
    asm volatile(
        "mma.sync.aligned.m16n8k16.row.col.f32.f16.f16.f32 "
        "{%0,%1,%2,%3}, {%4,%5,%6,%7}, {%8,%9}, {%0,%1,%2,%3};"
        : "+f"(c[0]), "+f"(c[1]), "+f"(c[2]), "+f"(c[3])
        : "r"(a[0]), "r"(a[1]), "r"(a[2]), "r"(a[3]), "r"(b0), "r"(b1));
}

__device__ __forceinline__ void split_pack_h(float x, float y,
                                             uint32_t& hi, uint32_t& lo) {
    __half hx = __float2half_rn(x);
    __half hy = __float2half_rn(y);
    __half lx = __float2half_rn(x - __half2float(hx));
    __half ly = __float2half_rn(y - __half2float(hy));
    hi = ((uint32_t)__half_as_ushort(hy) << 16) | (uint32_t)__half_as_ushort(hx);
    lo = ((uint32_t)__half_as_ushort(ly) << 16) | (uint32_t)__half_as_ushort(lx);
}

__device__ __forceinline__ uint32_t pack_h(float x, float y) {
    __half hx = __float2half_rn(x);
    __half hy = __float2half_rn(y);
    return ((uint32_t)__half_as_ushort(hy) << 16) | (uint32_t)__half_as_ushort(hx);
}

__global__ __launch_bounds__(256, 4)
void mma_gemm_kernel(const float* __restrict__ A,
                     const float* __restrict__ B1, __half* __restrict__ C1h,
                     int N1, int nT1,
                     const float* __restrict__ B2, const float* __restrict__ bias,
                     const float* __restrict__ bias2, float* __restrict__ C2,
                     int N2, int nT2, int gateSkip, int M) {
    extern __shared__ char smem[];
    const uint32_t sbase = (uint32_t)__cvta_generic_to_shared(smem);
    const int tid = threadIdx.x;
    const int lane = tid & 31;
    const int wid = tid >> 5;
    const int row0 = blockIdx.x * 64;

    // ---- load + split A tile ONCE: 64 rows x 128 k --------------------------
    {
        uint32_t* shi = (uint32_t*)(smem + OFF_A_HI);
        uint32_t* slo = (uint32_t*)(smem + OFF_A_LO);
#pragma unroll
        for (int p = 0; p < 8; p++) {
            int idx = p * 256 + tid;          // float4 index: 64 rows x 32
            int row = idx >> 5;
            int k4 = idx & 31;
            int gr = row0 + row;
            float4 v = make_float4(0.f, 0.f, 0.f, 0.f);
            if (gr < M) v = *(const float4*)(A + (size_t)gr * HDIM + k4 * 4);
            uint32_t h0, l0, h1, l1;
            split_pack_h(v.x, v.y, h0, l0);
            split_pack_h(v.z, v.w, h1, l1);
            int o = row * (SROW / 2) + k4 * 2;
            shi[o] = h0; shi[o + 1] = h1;
            slo[o] = l0; slo[o + 1] = l1;
        }
    }

    const int wm = wid >> 1;                  // 0..3 -> rows wm*16
    const int wn = wid & 1;                   // 0..1 -> cols wn*32
    const int a_row_in = ((lane >> 3) & 1) * 8 + (lane & 7);
    const int a_kh = (lane >> 4) * 8;
    const int b_row_in = ((lane >> 4) & 1) * 8 + (lane & 7);
    const int b_kh = ((lane >> 3) & 1) * 8;

    const int nTot = nT1 + nT2;
    for (int t = 0; t < nTot; t++) {
        const bool ph1 = (t < nT1);
        const int tt = ph1 ? t : t - nT1;
        const float* Bp = ph1 ? B1 : B2;
        const int brow0 = ph1 ? tt * 64
                              : (gateSkip ? ((tt < 2) ? tt * 64 : (tt + 2) * 64)
                                          : tt * 64);
        const int ccol0 = tt * 64;

        if (t > 0) __syncthreads();   // previous compute done before B overwrite

        // ---- load B tile (single fp16 copy): 64 rows x 128 k ----------------
        {
            uint32_t* sb = (uint32_t*)(smem + OFF_B);
#pragma unroll
            for (int p = 0; p < 8; p++) {
                int idx = p * 256 + tid;
                int row = idx >> 5;
                int k4 = idx & 31;
                float4 v = *(const float4*)(Bp + (size_t)(brow0 + row) * HDIM + k4 * 4);
                int o = row * (SROW / 2) + k4 * 2;
                sb[o] = pack_h(v.x, v.y);
                sb[o + 1] = pack_h(v.z, v.w);
            }
        }
        __syncthreads();

        float acc[4][4];
#pragma unroll
        for (int j = 0; j < 4; j++)
#pragma unroll
            for (int q = 0; q < 4; q++) acc[j][q] = 0.0f;

#pragma unroll 2
        for (int kc = 0; kc < 8; kc++) {
            const int k0 = kc * 16;
            uint32_t ah[4], al[4];
            {
                int row = wm * 16 + a_row_in;
                uint32_t off = (uint32_t)(row * (SROW * 2) + (k0 + a_kh) * 2);
                ldsm4(ah[0], ah[1], ah[2], ah[3], sbase + OFF_A_HI + off);
                ldsm4(al[0], al[1], al[2], al[3], sbase + OFF_A_LO + off);
            }
            uint32_t bh[2][4];
#pragma unroll
            for (int p = 0; p < 2; p++) {
                int row = wn * 32 + p * 16 + b_row_in;
                uint32_t off = (uint32_t)(row * (SROW * 2) + (k0 + b_kh) * 2);
                ldsm4(bh[p][0], bh[p][1], bh[p][2], bh[p][3], sbase + OFF_B + off);
            }
#pragma unroll
            for (int j = 0; j < 4; j++) {
                const int p = j >> 1;
                const int s = (j & 1) * 2;
                mma_f16(acc[j], ah, bh[p][s], bh[p][s + 1]);
                mma_f16(acc[j], al, bh[p][s], bh[p][s + 1]);
            }
        }

        // ---- store tile -----------------------------------------------------
        if (ph1) {
#pragma unroll
            for (int j = 0; j < 4; j++) {
                int cb = ccol0 + wn * 32 + j * 8 + (lane & 3) * 2;
                int ra = row0 + wm * 16 + (lane >> 2);
                if (ra < M) {
                    __half2 hv = __floats2half2_rn(acc[j][0], acc[j][1]);
                    *(__half2*)(C1h + (size_t)ra * N1 + cb) = hv;
                }
                int rb = ra + 8;
                if (rb < M) {
                    __half2 hv = __floats2half2_rn(acc[j][2], acc[j][3]);
                    *(__half2*)(C1h + (size_t)rb * N1 + cb) = hv;
                }
            }
        } else {
#pragma unroll
            for (int j = 0; j < 4; j++) {
                int cloc = wn * 32 + j * 8 + (lane & 3) * 2;
                int cb = ccol0 + cloc;
                int bidx = brow0 + cloc;
                float b0 = 0.f, b1 = 0.f;
                if (bias)  { b0 += __ldg(bias + bidx);  b1 += __ldg(bias + bidx + 1); }
                if (bias2) { b0 += __ldg(bias2 + bidx); b1 += __ldg(bias2 + bidx + 1); }
                int ra = row0 + wm * 16 + (lane >> 2);
                if (ra < M) {
                    float2 o = make_float2(acc[j][0] + b0, acc[j][1] + b1);
                    *(float2*)(C2 + (size_t)ra * N2 + cb) = o;
                }
                int rb = ra + 8;
                if (rb < M) {
                    float2 o = make_float2(acc[j][2] + b0, acc[j][3] + b1);
                    *(float2*)(C2 + (size_t)rb * N2 + cb) = o;
                }
            }
        }
    }
}

// ---------------- GRU elementwise (standalone, high occupancy) ----------------
__global__ void gru_elem_kernel(const float* __restrict__ x, int M) {
    int i = blockIdx.x * blockDim.x + threadIdx.x;
    if (i >= M * HDIM) return;
    int row = i >> 7;
    int j = i & 127;
    const float* gir = g_gi + (size_t)row * (3 * HDIM);
    const float* ghr = g_gh + (size_t)row * (3 * HDIM);
    float r = 1.0f / (1.0f + __expf(-(gir[j] + ghr[j])));
    float z = 1.0f / (1.0f + __expf(-(gir[j + 128] + ghr[j + 128])));
    float ng = tanhf(gir[j + 256] + r * ghr[j + 256]);
    g_hconv[i] = (1.0f - z) * ng + z * x[i];
}

// ---------------- LSTM elementwise (compact [i,g,o]) + ReLU -------------------
__global__ void lstm_elem_kernel(float* __restrict__ out, int M) {
    int i = blockIdx.x * blockDim.x + threadIdx.x;
    if (i >= M * HDIM) return;
    int row = i >> 7;
    int j = i & 127;
    const float* g = g_gates + (size_t)row * (3 * HDIM);
    float ig = g[j];
    float gg = g[j + 128];
    float og = g[j + 256];
    float c = (1.0f / (1.0f + __expf(-ig))) * tanhf(gg);
    float h = (1.0f / (1.0f + __expf(-og))) * tanhf(c);
    out[i] = fmaxf(h, 0.0f);
}

// ---------------- host orchestration -----------------------------------------
extern "C" void kernel_launch(void* const* d_in, const int* in_sizes, int n_in,
                              void* d_out, int out_size) {
    const float* x = (const float*)d_in[0];
    const void* edges = d_in[1];
    const float* W = (const float*)d_in[2];
    const float* gru_w_ih = (const float*)d_in[3];
    const float* gru_w_hh = (const float*)d_in[4];
    const float* gru_b_ih = (const float*)d_in[5];
    const float* gru_b_hh = (const float*)d_in[6];
    const float* lstm_w_ih = (const float*)d_in[7];
    // d_in[8] lstm_w_hh dead (h0 = 0)
    const float* lstm_b_ih = (const float*)d_in[9];
    const float* lstm_b_hh = (const float*)d_in[10];
    float* out = (float*)d_out;

    const int M = in_sizes[0] / HDIM;
    const int E = in_sizes[1] / 2;

    float *pgh, *pagg, *pgi, *phc, *pgates, *pwt;
    __half* pmh;
    cudaGetSymbolAddress((void**)&pmh, g_mh);
    cudaGetSymbolAddress((void**)&pgh, g_gh);
    cudaGetSymbolAddress((void**)&pagg, g_agg);
    cudaGetSymbolAddress((void**)&pgi, g_gi);
    cudaGetSymbolAddress((void**)&phc, g_hconv);
    cudaGetSymbolAddress((void**)&pgates, g_gates);
    cudaGetSymbolAddress((void**)&pwt, g_wt);

    cudaFuncSetAttribute(mma_gemm_kernel,
                         cudaFuncAttributeMaxDynamicSharedMemorySize, SMEM_BYTES);

    const int rowTiles = (M + 63) / 64;

    // 1) prep
    detect_kernel<<<1, 1>>>(edges);
    zero_deg_kernel<<<(M + 255) / 256, 256>>>(M);
    transposeW_kernel<<<(HDIM * HDIM + 255) / 256, 256>>>(W);

    // 2) merged: m(fp16) = x @ W  AND  gh = x @ gru_w_hh^T + b_hh  (A once)
    mma_gemm_kernel<<<rowTiles, 256, SMEM_BYTES>>>(
        x,
        pwt, pmh, HDIM, 2,
        gru_w_hh, gru_b_hh, (const float*)0, pgh, 3 * HDIM, 6,
        0, M);

    // 3) CSR build + gather (fp16 messages, mean fused)
    hist_kernel<<<4096, 256>>>(edges, E);
    scan_kernel<<<1, 1024>>>(M);
    fill_kernel<<<4096, 256>>>(edges, E);
    gather_kernel<<<(M * 32 + 255) / 256, 256>>>(pmh, M);

    // 4) gi = agg @ gru_w_ih^T + b_ih
    mma_gemm_kernel<<<rowTiles, 256, SMEM_BYTES>>>(
        pagg,
        (const float*)0, (__half*)0, 0, 0,
        gru_w_ih, gru_b_ih, (const float*)0, pgi, 3 * HDIM, 6,
        0, M);

    // 5) GRU combine -> hconv
    gru_elem_kernel<<<(M * HDIM + 255) / 256, 256>>>(x, M);

    // 6) gates = hconv @ lstm_w_ih^T + b (f-gate skipped, compact [i,g,o])
    mma_gemm_kernel<<<rowTiles, 256, SMEM_BYTES>>>(
        phc,
        (const float*)0, (__half*)0, 0, 0,
        lstm_w_ih, lstm_b_ih, lstm_b_hh, pgates, 3 * HDIM, 6,
        1, M);

    // 7) LSTM + ReLU -> out
    lstm_elem_kernel<<<(M * HDIM + 255) / 256, 256>>>(out, M);
}